// round 13
// baseline (speedup 1.0000x reference)
#include <cuda_runtime.h>
#include <cuda_bf16.h>
#include <cstdint>
#include <math.h>

#define DIMS    1024
#define SEQ     2048
#define BATCH   2
#define NHEADS  16
#define HDIM    64
#define QKVLD   3072

// ---------------------------------------------------------------------------
// Scratch (allocation-free rule: __device__ globals)
// ---------------------------------------------------------------------------
__device__ float g_qkv[(size_t)BATCH * SEQ * QKVLD];
__device__ float g_ctx[(size_t)BATCH * SEQ * DIMS];
__device__ float g_wqkvT[(size_t)QKVLD * DIMS];
__device__ float g_wprojT[(size_t)DIMS * DIMS];

__device__ __forceinline__ uint32_t f32_to_tf32(float f) {
    uint32_t u;
    asm("cvt.rna.tf32.f32 %0, %1;" : "=r"(u) : "f"(f));
    return u;
}

__device__ __forceinline__ void mma_tf32(float* d, const uint32_t* a, const uint32_t* b) {
    asm volatile(
        "mma.sync.aligned.m16n8k8.row.col.f32.tf32.tf32.f32 "
        "{%0,%1,%2,%3}, {%4,%5,%6,%7}, {%8,%9}, {%0,%1,%2,%3};"
        : "+f"(d[0]), "+f"(d[1]), "+f"(d[2]), "+f"(d[3])
        : "r"(a[0]), "r"(a[1]), "r"(a[2]), "r"(a[3]), "r"(b[0]), "r"(b[1]));
}

// bf16 m16n8k16 mma (sm_80+)
__device__ __forceinline__ void mma_bf16(float* d, const uint32_t* a, const uint32_t* b) {
    asm volatile(
        "mma.sync.aligned.m16n8k16.row.col.f32.bf16.bf16.f32 "
        "{%0,%1,%2,%3}, {%4,%5,%6,%7}, {%8,%9}, {%0,%1,%2,%3};"
        : "+f"(d[0]), "+f"(d[1]), "+f"(d[2]), "+f"(d[3])
        : "r"(a[0]), "r"(a[1]), "r"(a[2]), "r"(a[3]), "r"(b[0]), "r"(b[1]));
}

// pack two floats to bf16x2 word: low half = e (even k), high half = o (odd k).
__device__ __forceinline__ uint32_t pack2_bf16(float e, float o) {
    __nv_bfloat162 p = __float22bfloat162_rn(make_float2(e, o));
    return *reinterpret_cast<uint32_t*>(&p);
}
__device__ __forceinline__ float bf16_round(float x) {
    return __bfloat162float(__float2bfloat16_rn(x));
}

// cp.async 16B (sm_80+)
__device__ __forceinline__ void cp_async16(uint32_t smem_addr, const void* gptr) {
    asm volatile("cp.async.cg.shared.global [%0], [%1], 16;"
                 :: "r"(smem_addr), "l"(gptr));
}
#define CP_COMMIT() asm volatile("cp.async.commit_group;" ::: "memory")
#define CP_WAIT0()  asm volatile("cp.async.wait_group 0;" ::: "memory")

// ---------------------------------------------------------------------------
// Weight transpose (unchanged).
// ---------------------------------------------------------------------------
__global__ __launch_bounds__(256) void transpose_k(
    const float* __restrict__ in, float* __restrict__ out, int R, int C)
{
    __shared__ float t[32][33];
    int x = blockIdx.x * 32 + threadIdx.x;
    int y = blockIdx.y * 32 + threadIdx.y;
#pragma unroll
    for (int j = 0; j < 32; j += 8)
        t[threadIdx.y + j][threadIdx.x] = in[(size_t)(y + j) * C + x];
    __syncthreads();
    int x2 = blockIdx.y * 32 + threadIdx.x;
    int y2 = blockIdx.x * 32 + threadIdx.y;
#pragma unroll
    for (int j = 0; j < 32; j += 8)
        out[(size_t)(y2 + j) * R + x2] = t[threadIdx.x][threadIdx.y + j];
}

// ---------------------------------------------------------------------------
// tf32 mma.sync GEMM (unchanged — validated).
// ---------------------------------------------------------------------------
#define CH_K 16

template <bool HAS_BIAS>
__global__ __launch_bounds__(256) void gemm_mma(
    const float* __restrict__ A, const float* __restrict__ BT,
    const float* __restrict__ bias, float* __restrict__ C,
    int M, int N, int K)
{
    __shared__ uint32_t sA[2][128 * CH_K];
    __shared__ uint32_t sB[2][128 * CH_K];

    const int tid   = threadIdx.x;
    const int lane  = tid & 31;
    const int wid   = tid >> 5;
    const int warpM = wid >> 2;
    const int warpN = wid & 3;
    const int m0 = blockIdx.y * 128;
    const int n0 = blockIdx.x * 128;

    const float* agp[2];
    const float* bgp[2];
    int abase[2], bbase[2], arot[2], brot[2];
#pragma unroll
    for (int i = 0; i < 2; i++) {
        const int idx = tid + i * 256;
        const int row = idx >> 2;
        const int k0  = (idx & 3) << 2;
        agp[i] = A + (size_t)(m0 + row) * K + k0;
        {
            const int mt = row >> 4, rr = row & 15, s = k0 >> 3;
            const int bi = mt * 2 + s;
            const int reg = (rr >> 3) + 2 * ((k0 >> 2) & 1);
            arot[i]  = (bi & 1) * 2;
            abase[i] = (bi * 32 + (rr & 7) * 4) * 4 + reg;
        }
        bgp[i] = BT + (size_t)(n0 + row) * K + k0;
        {
            const int nt = row >> 3, nn = row & 7, s = k0 >> 3;
            const int bi = nt * 2 + s;
            const int reg = (k0 >> 2) & 1;
            brot[i]  = (bi & 1) * 2;
            bbase[i] = (bi * 32 + nn * 4) * 2 + reg;
        }
    }

    float acc[4][4][4];
#pragma unroll
    for (int i = 0; i < 4; i++)
#pragma unroll
        for (int j = 0; j < 4; j++)
#pragma unroll
            for (int r = 0; r < 4; r++) acc[i][j][r] = 0.f;

    float4 ra[2], rb[2];
#pragma unroll
    for (int i = 0; i < 2; i++) {
        ra[i] = *(const float4*)agp[i];
        rb[i] = *(const float4*)bgp[i];
    }
#pragma unroll
    for (int i = 0; i < 2; i++) {
        const float av[4] = {ra[i].x, ra[i].y, ra[i].z, ra[i].w};
        const float bv[4] = {rb[i].x, rb[i].y, rb[i].z, rb[i].w};
#pragma unroll
        for (int q = 0; q < 4; q++) {
            sA[0][abase[i] + ((q ^ arot[i]) << 2)] = f32_to_tf32(av[q]);
            sB[0][bbase[i] + ((q ^ brot[i]) << 1)] = f32_to_tf32(bv[q]);
        }
    }
    __syncthreads();

    const int nch = K / CH_K;
    for (int c = 0; c < nch; c++) {
        const int cur = c & 1;
        if (c + 1 < nch) {
            const int ko = (c + 1) * CH_K;
#pragma unroll
            for (int i = 0; i < 2; i++) {
                ra[i] = *(const float4*)(agp[i] + ko);
                rb[i] = *(const float4*)(bgp[i] + ko);
            }
        }

#pragma unroll
        for (int s = 0; s < 2; s++) {
            uint32_t af[4][4];
            uint32_t bf[4][2];
#pragma unroll
            for (int i = 0; i < 4; i++) {
                const int bi = (warpM * 4 + i) * 2 + s;
                const int l  = lane ^ ((bi & 1) * 2);
                *(uint4*)af[i] = *(const uint4*)&sA[cur][(bi * 32 + l) * 4];
            }
#pragma unroll
            for (int j = 0; j < 4; j++) {
                const int bi = (warpN * 4 + j) * 2 + s;
                const int l  = lane ^ ((bi & 1) * 2);
                *(uint2*)bf[j] = *(const uint2*)&sB[cur][(bi * 32 + l) * 2];
            }
#pragma unroll
            for (int i = 0; i < 4; i++)
#pragma unroll
                for (int j = 0; j < 4; j++)
                    mma_tf32(acc[i][j], af[i], bf[j]);
        }

        if (c + 1 < nch) {
            const int nxt = cur ^ 1;
#pragma unroll
            for (int i = 0; i < 2; i++) {
                const float av[4] = {ra[i].x, ra[i].y, ra[i].z, ra[i].w};
                const float bv[4] = {rb[i].x, rb[i].y, rb[i].z, rb[i].w};
#pragma unroll
                for (int q = 0; q < 4; q++) {
                    sA[nxt][abase[i] + ((q ^ arot[i]) << 2)] = f32_to_tf32(av[q]);
                    sB[nxt][bbase[i] + ((q ^ brot[i]) << 1)] = f32_to_tf32(bv[q]);
                }
            }
        }
        __syncthreads();
    }

#pragma unroll
    for (int i = 0; i < 4; i++) {
        const int row = m0 + warpM * 64 + i * 16 + (lane >> 2);
#pragma unroll
        for (int j = 0; j < 4; j++) {
            const int col = n0 + warpN * 32 + j * 8 + (lane & 3) * 2;
            float2 v0 = make_float2(acc[i][j][0], acc[i][j][1]);
            float2 v1 = make_float2(acc[i][j][2], acc[i][j][3]);
            if (HAS_BIAS) {
                const float b0 = bias[col], b1 = bias[col + 1];
                v0.x += b0; v0.y += b1;
                v1.x += b0; v1.y += b1;
            }
            *(float2*)(C + (size_t)row * N + col) = v0;
            *(float2*)(C + (size_t)(row + 8) * N + col) = v1;
        }
    }
}

// ---------------------------------------------------------------------------
// Tensor-core flash attention, split-bf16 m16n8k16, Br=64 Bc=64,
// cp.async depth-1 pipeline: raw f32 K/V tiles DMA'd during compute of the
// previous iteration; convert (raw -> split-bf16 frag layout) is smem->smem.
// smem: 48 KB converted (Q/K/V hi+lo) + 34 KB raw (stride-68 rows) = 82 KB
// -> 2 CTAs/SM, __launch_bounds__(128, 2).
// Fragment layouts identical to R11 (validated).
// ---------------------------------------------------------------------------
#define RAWK 12288            // word offset of raw K (64 rows x 68 f32)
#define RAWV (12288 + 64*68)  // raw V
#define FSM_WORDS (RAWV + 64*68)   // 20992 words = 83968 B

__global__ __launch_bounds__(128, 2) void flash_mma(
    const float* __restrict__ qkv, float* __restrict__ ctx)
{
    extern __shared__ uint32_t fsm[];
    uint32_t* sQh = fsm;             // 2048 words
    uint32_t* sQl = fsm + 2048;
    uint32_t* sKh = fsm + 4096;
    uint32_t* sKl = fsm + 6144;
    uint32_t* sVh = fsm + 8192;
    uint32_t* sVl = fsm + 10240;
    float* rawK = (float*)(fsm + RAWK);
    float* rawV = (float*)(fsm + RAWV);
    const uint32_t smem_base = (uint32_t)__cvta_generic_to_shared(fsm);

    const int tid  = threadIdx.x;
    const int lane = tid & 31;
    const int wid  = tid >> 5;
    const int b = blockIdx.z, h = blockIdx.y;
    const int q0 = blockIdx.x * 64;

    const float* Qg = qkv + (size_t)b * SEQ * QKVLD + h * HDIM;
    const float* Kg = Qg + DIMS;
    const float* Vg = Qg + 2 * DIMS;

    const int slotC = ((lane >> 2) << 2) | ((lane & 3) ^ ((lane >> 3) & 3));
    const int aoff = slotC ^ (((wid >> 1) & 1) << 2);
    int boff[8];
#pragma unroll
    for (int nt = 0; nt < 8; nt++)
        boff[nt] = slotC ^ ((((nt >> 1) & 1) << 2) | (((nt >> 2) & 1) << 3));

    // ---- stage Q (scaled 0.125, hi/lo bf16) : direct from gmem, once ----
#pragma unroll
    for (int i = 0; i < 8; i++) {
        const int idx = tid + i * 128;
        const int row = idx & 63, k0 = (idx >> 6) * 4;
        float4 v = *(const float4*)(Qg + (size_t)(q0 + row) * QKVLD + k0);
        const float x0 = v.x * 0.125f, x1 = v.y * 0.125f;
        const float x2 = v.z * 0.125f, x3 = v.w * 0.125f;
        const int bi = (row >> 4) * 4 + (k0 >> 4);
        const int rot = (((bi >> 3) & 1) << 2) | (((bi >> 4) & 1) << 3);
        const int scr = ((row & 7) >> 1) & 3;
        const int p0 = (k0 >> 1) & 3;
        const int reg = ((row >> 3) & 1) + 2 * ((k0 >> 3) & 1);
        const int s0 = (((row & 7) << 2) | (p0 ^ scr)) ^ rot;
        const int s1 = (((row & 7) << 2) | ((p0 + 1) ^ scr)) ^ rot;
        const int a0 = (bi * 32 + s0) * 4 + reg;
        const int a1 = (bi * 32 + s1) * 4 + reg;
        sQh[a0] = pack2_bf16(x0, x1);
        sQh[a1] = pack2_bf16(x2, x3);
        sQl[a0] = pack2_bf16(x0 - bf16_round(x0), x1 - bf16_round(x1));
        sQl[a1] = pack2_bf16(x2 - bf16_round(x2), x3 - bf16_round(x3));
    }

    // per-thread cp.async geometry: 8 K rows-slices + 8 V, 16B each
    const int cpn  = tid & 63;              // row 0..63
    const int cpk0 = (tid >> 6) * 4;        // 0 or 4 (then +8 per i)

    // ---- prefetch iter 0 raw tiles ----
#pragma unroll
    for (int i = 0; i < 8; i++) {
        const int k0 = cpk0 + i * 8;        // 0..60, two threads cover 64
        cp_async16(smem_base + (RAWK + cpn * 68 + k0) * 4,
                   Kg + (size_t)cpn * QKVLD + k0);
        cp_async16(smem_base + (RAWV + cpn * 68 + k0) * 4,
                   Vg + (size_t)cpn * QKVLD + k0);
    }
    CP_COMMIT();

    float oacc[8][4];
    float m_run[2], l_run[2];
#pragma unroll
    for (int nt = 0; nt < 8; nt++)
#pragma unroll
        for (int r = 0; r < 4; r++) oacc[nt][r] = 0.f;
    m_run[0] = m_run[1] = -1e30f;
    l_run[0] = l_run[1] = 0.f;

    for (int it = 0; it < SEQ / 64; it++) {
        // raw tiles for this iter arrived; conv buffers free (prev compute done)
        CP_WAIT0();
        __syncthreads();

        // ---- convert K: raw f32 -> split-bf16 frag layout ----
#pragma unroll
        for (int i = 0; i < 8; i++) {
            const int idx = tid + i * 128;
            const int n = idx & 63, k0 = (idx >> 6) * 4;
            float4 v = *(const float4*)(rawK + n * 68 + k0);
            const int bi = (n >> 3) * 4 + (k0 >> 4);
            const int rot = (((bi >> 3) & 1) << 2) | (((bi >> 4) & 1) << 3);
            const int scr = ((n & 7) >> 1) & 3;
            const int p0 = (k0 >> 1) & 3;
            const int reg = (k0 >> 3) & 1;
            const int s0 = (((n & 7) << 2) | (p0 ^ scr)) ^ rot;
            const int s1 = (((n & 7) << 2) | ((p0 + 1) ^ scr)) ^ rot;
            const int a0 = (bi * 32 + s0) * 2 + reg;
            const int a1 = (bi * 32 + s1) * 2 + reg;
            sKh[a0] = pack2_bf16(v.x, v.y);
            sKh[a1] = pack2_bf16(v.z, v.w);
            sKl[a0] = pack2_bf16(v.x - bf16_round(v.x), v.y - bf16_round(v.y));
            sKl[a1] = pack2_bf16(v.z - bf16_round(v.z), v.w - bf16_round(v.w));
        }
        // ---- convert V (n=hd, k=kv; kv-pairs packed) ----
#pragma unroll
        for (int i = 0; i < 4; i++) {
            const int idx = tid + i * 128;
            const int hd4 = idx & 15, kvp = idx >> 4;
            const int kvr = kvp * 2;
            float4 ve = *(const float4*)(rawV + kvr * 68 + hd4 * 4);
            float4 vo = *(const float4*)(rawV + (kvr + 1) * 68 + hd4 * 4);
            const float es[4] = {ve.x, ve.y, ve.z, ve.w};
            const float os[4] = {vo.x, vo.y, vo.z, vo.w};
            const int pp  = (kvr >> 1) & 3;
            const int reg = (kvr >> 3) & 1;
#pragma unroll
            for (int q = 0; q < 4; q++) {
                const int n = hd4 * 4 + q;
                const int bi = (n >> 3) * 4 + (kvr >> 4);
                const int rot = (((bi >> 3) & 1) << 2) | (((bi >> 4) & 1) << 3);
                const int scr = ((n & 7) >> 1) & 3;
                const int sl = (((n & 7) << 2) | (pp ^ scr)) ^ rot;
                const int a = (bi * 32 + sl) * 2 + reg;
                sVh[a] = pack2_bf16(es[q], os[q]);
                sVl[a] = pack2_bf16(es[q] - bf16_round(es[q]),
                                    os[q] - bf16_round(os[q]));
            }
        }
        __syncthreads();   // conv ready; raw free for next prefetch

        // ---- prefetch next iter's raw tiles (overlaps compute below) ----
        if (it + 1 < SEQ / 64) {
            const int kv1 = (it + 1) * 64;
#pragma unroll
            for (int i = 0; i < 8; i++) {
                const int k0 = cpk0 + i * 8;
                cp_async16(smem_base + (RAWK + cpn * 68 + k0) * 4,
                           Kg + (size_t)(kv1 + cpn) * QKVLD + k0);
                cp_async16(smem_base + (RAWV + cpn * 68 + k0) * 4,
                           Vg + (size_t)(kv1 + cpn) * QKVLD + k0);
            }
            CP_COMMIT();
        }

        // ---- S = (Q*scale) @ K^T : 4 k16-steps x 8 kv-tiles, 3-term ----
        float sf[8][4];
#pragma unroll
        for (int nt = 0; nt < 8; nt++)
#pragma unroll
            for (int r = 0; r < 4; r++) sf[nt][r] = 0.f;

#pragma unroll
        for (int s = 0; s < 4; s++) {
            uint32_t aH[4], aL[4];
            *(uint4*)aH = *(const uint4*)&sQh[((wid * 4 + s) * 32 + aoff) * 4];
            *(uint4*)aL = *(const uint4*)&sQl[((wid * 4 + s) * 32 + aoff) * 4];
#pragma unroll
            for (int nt = 0; nt < 8; nt++) {
                uint32_t bH[2], bL[2];
                *(uint2*)bH = *(const uint2*)&sKh[((nt * 4 + s) * 32 + boff[nt]) * 2];
                *(uint2*)bL = *(const uint2*)&sKl[((nt * 4 + s) * 32 + boff[nt]) * 2];
                mma_bf16(sf[nt], aH, bH);
                mma_bf16(sf[nt], aH, bL);
                mma_bf16(sf[nt], aL, bH);
            }
        }

        // ---- online softmax (rows lane>>2, +8) ----
#pragma unroll
        for (int hf = 0; hf < 2; hf++) {
            float tm = -1e30f;
#pragma unroll
            for (int nt = 0; nt < 8; nt++)
                tm = fmaxf(tm, fmaxf(sf[nt][hf * 2], sf[nt][hf * 2 + 1]));
            tm = fmaxf(tm, __shfl_xor_sync(0xffffffffu, tm, 1));
            tm = fmaxf(tm, __shfl_xor_sync(0xffffffffu, tm, 2));
            const float mn  = fmaxf(m_run[hf], tm);
            const float fac = __expf(m_run[hf] - mn);
            float sum = 0.f;
#pragma unroll
            for (int nt = 0; nt < 8; nt++) {
#pragma unroll
                for (int j = 0; j < 2; j++) {
                    const float p = __expf(sf[nt][hf * 2 + j] - mn);
                    sf[nt][hf * 2 + j] = p;
                    sum += p;
                }
            }
            sum += __shfl_xor_sync(0xffffffffu, sum, 1);
            sum += __shfl_xor_sync(0xffffffffu, sum, 2);
            l_run[hf] = l_run[hf] * fac + sum;
            m_run[hf] = mn;
#pragma unroll
            for (int nt = 0; nt < 8; nt++) {
                oacc[nt][hf * 2]     *= fac;
                oacc[nt][hf * 2 + 1] *= fac;
            }
        }

        // ---- O += P @ V: P C-frag -> bf16 A-frag by packing ----
#pragma unroll
        for (int s = 0; s < 4; s++) {
            const float* p0 = sf[2 * s];
            const float* p1 = sf[2 * s + 1];
            uint32_t aH[4], aL[4];
            aH[0] = pack2_bf16(p0[0], p0[1]);
            aH[1] = pack2_bf16(p0[2], p0[3]);
            aH[2] = pack2_bf16(p1[0], p1[1]);
            aH[3] = pack2_bf16(p1[2], p1[3]);
            aL[0] = pack2_bf16(p0[0] - bf16_round(p0[0]), p0[1] - bf16_round(p0[1]));
            aL[1] = pack2_bf16(p0[2] - bf16_round(p0[2]), p0[3] - bf16_round(p0[3]));
            aL[2] = pack2_bf16(p1[0] - bf16_round(p1[0]), p1[1] - bf16_round(p1[1]));
            aL[3] = pack2_bf16(p1[2] - bf16_round(p1[2]), p1[3] - bf16_round(p1[3]));
#pragma unroll
            for (int nt = 0; nt < 8; nt++) {
                uint32_t vH[2], vL[2];
                *(uint2*)vH = *(const uint2*)&sVh[((nt * 4 + s) * 32 + boff[nt]) * 2];
                *(uint2*)vL = *(const uint2*)&sVl[((nt * 4 + s) * 32 + boff[nt]) * 2];
                mma_bf16(oacc[nt], aH, vH);
                mma_bf16(oacc[nt], aH, vL);
                mma_bf16(oacc[nt], aL, vH);
            }
        }
    }

    // ---- normalize + write ctx[b][q][h*64 + d] ----
    const float inv0 = 1.0f / l_run[0];
    const float inv1 = 1.0f / l_run[1];
    const int row0 = q0 + wid * 16 + (lane >> 2);
#pragma unroll
    for (int nt = 0; nt < 8; nt++) {
        const int col = h * HDIM + nt * 8 + 2 * (lane & 3);
        *(float2*)(ctx + ((size_t)b * SEQ + row0) * DIMS + col) =
            make_float2(oacc[nt][0] * inv0, oacc[nt][1] * inv0);
        *(float2*)(ctx + ((size_t)b * SEQ + row0 + 8) * DIMS + col) =
            make_float2(oacc[nt][2] * inv1, oacc[nt][3] * inv1);
    }
}

// ---------------------------------------------------------------------------
extern "C" void kernel_launch(void* const* d_in, const int* in_sizes, int n_in,
                              void* d_out, int out_size)
{
    const float* x      = (const float*)d_in[0];
    const float* w_qkv  = (const float*)d_in[1];
    const float* w_proj = (const float*)d_in[2];
    const float* b_proj = (const float*)d_in[3];
    float* out = (float*)d_out;

    float *qkv, *ctx, *wqkvT, *wprojT;
    cudaGetSymbolAddress((void**)&qkv, g_qkv);
    cudaGetSymbolAddress((void**)&ctx, g_ctx);
    cudaGetSymbolAddress((void**)&wqkvT, g_wqkvT);
    cudaGetSymbolAddress((void**)&wprojT, g_wprojT);

    const int M = BATCH * SEQ;

    transpose_k<<<dim3(QKVLD / 32, DIMS / 32), dim3(32, 8)>>>(w_qkv, wqkvT, DIMS, QKVLD);
    transpose_k<<<dim3(DIMS / 32, DIMS / 32), dim3(32, 8)>>>(w_proj, wprojT, DIMS, DIMS);

    gemm_mma<false><<<dim3(QKVLD / 128, M / 128), 256>>>(
        x, wqkvT, nullptr, qkv, M, QKVLD, DIMS);

    const int fsmem = FSM_WORDS * 4;   // 83968 B
    cudaFuncSetAttribute(flash_mma, cudaFuncAttributeMaxDynamicSharedMemorySize,
                         fsmem);
    flash_mma<<<dim3(SEQ / 64, NHEADS, BATCH), 128, fsmem>>>(qkv, ctx);

    gemm_mma<true><<<dim3(DIMS / 128, M / 128), 256>>>(
        ctx, wprojT, b_proj, out, M, DIMS, DIMS);
}

// round 15
// speedup vs baseline: 1.4535x; 1.4535x over previous
#include <cuda_runtime.h>
#include <cuda_bf16.h>
#include <cstdint>
#include <math.h>

#define DIMS    1024
#define SEQ     2048
#define BATCH   2
#define NHEADS  16
#define HDIM    64
#define QKVLD   3072

// ---------------------------------------------------------------------------
// Scratch (allocation-free rule: __device__ globals)
// ---------------------------------------------------------------------------
__device__ float g_qkv[(size_t)BATCH * SEQ * QKVLD];
__device__ float g_ctx[(size_t)BATCH * SEQ * DIMS];
__device__ float g_wqkvT[(size_t)QKVLD * DIMS];
__device__ float g_wprojT[(size_t)DIMS * DIMS];

__device__ __forceinline__ uint32_t f32_to_tf32(float f) {
    uint32_t u;
    asm("cvt.rna.tf32.f32 %0, %1;" : "=r"(u) : "f"(f));
    return u;
}

__device__ __forceinline__ void mma_tf32(float* d, const uint32_t* a, const uint32_t* b) {
    asm volatile(
        "mma.sync.aligned.m16n8k8.row.col.f32.tf32.tf32.f32 "
        "{%0,%1,%2,%3}, {%4,%5,%6,%7}, {%8,%9}, {%0,%1,%2,%3};"
        : "+f"(d[0]), "+f"(d[1]), "+f"(d[2]), "+f"(d[3])
        : "r"(a[0]), "r"(a[1]), "r"(a[2]), "r"(a[3]), "r"(b[0]), "r"(b[1]));
}

// bf16 m16n8k16 mma (sm_80+)
__device__ __forceinline__ void mma_bf16(float* d, const uint32_t* a, const uint32_t* b) {
    asm volatile(
        "mma.sync.aligned.m16n8k16.row.col.f32.bf16.bf16.f32 "
        "{%0,%1,%2,%3}, {%4,%5,%6,%7}, {%8,%9}, {%0,%1,%2,%3};"
        : "+f"(d[0]), "+f"(d[1]), "+f"(d[2]), "+f"(d[3])
        : "r"(a[0]), "r"(a[1]), "r"(a[2]), "r"(a[3]), "r"(b[0]), "r"(b[1]));
}

// pack two floats to bf16x2 word: low half = e (even k), high half = o (odd k).
__device__ __forceinline__ uint32_t pack2_bf16(float e, float o) {
    __nv_bfloat162 p = __float22bfloat162_rn(make_float2(e, o));
    return *reinterpret_cast<uint32_t*>(&p);
}
__device__ __forceinline__ float bf16_round(float x) {
    return __bfloat162float(__float2bfloat16_rn(x));
}

// ---------------------------------------------------------------------------
// Weight transpose (unchanged).
// ---------------------------------------------------------------------------
__global__ __launch_bounds__(256) void transpose_k(
    const float* __restrict__ in, float* __restrict__ out, int R, int C)
{
    __shared__ float t[32][33];
    int x = blockIdx.x * 32 + threadIdx.x;
    int y = blockIdx.y * 32 + threadIdx.y;
#pragma unroll
    for (int j = 0; j < 32; j += 8)
        t[threadIdx.y + j][threadIdx.x] = in[(size_t)(y + j) * C + x];
    __syncthreads();
    int x2 = blockIdx.y * 32 + threadIdx.x;
    int y2 = blockIdx.x * 32 + threadIdx.y;
#pragma unroll
    for (int j = 0; j < 32; j += 8)
        out[(size_t)(y2 + j) * R + x2] = t[threadIdx.x][threadIdx.y + j];
}

// ---------------------------------------------------------------------------
// tf32 mma.sync GEMM (unchanged — validated).
// ---------------------------------------------------------------------------
#define CH_K 16

template <bool HAS_BIAS>
__global__ __launch_bounds__(256) void gemm_mma(
    const float* __restrict__ A, const float* __restrict__ BT,
    const float* __restrict__ bias, float* __restrict__ C,
    int M, int N, int K)
{
    __shared__ uint32_t sA[2][128 * CH_K];
    __shared__ uint32_t sB[2][128 * CH_K];

    const int tid   = threadIdx.x;
    const int lane  = tid & 31;
    const int wid   = tid >> 5;
    const int warpM = wid >> 2;
    const int warpN = wid & 3;
    const int m0 = blockIdx.y * 128;
    const int n0 = blockIdx.x * 128;

    const float* agp[2];
    const float* bgp[2];
    int abase[2], bbase[2], arot[2], brot[2];
#pragma unroll
    for (int i = 0; i < 2; i++) {
        const int idx = tid + i * 256;
        const int row = idx >> 2;
        const int k0  = (idx & 3) << 2;
        agp[i] = A + (size_t)(m0 + row) * K + k0;
        {
            const int mt = row >> 4, rr = row & 15, s = k0 >> 3;
            const int bi = mt * 2 + s;
            const int reg = (rr >> 3) + 2 * ((k0 >> 2) & 1);
            arot[i]  = (bi & 1) * 2;
            abase[i] = (bi * 32 + (rr & 7) * 4) * 4 + reg;
        }
        bgp[i] = BT + (size_t)(n0 + row) * K + k0;
        {
            const int nt = row >> 3, nn = row & 7, s = k0 >> 3;
            const int bi = nt * 2 + s;
            const int reg = (k0 >> 2) & 1;
            brot[i]  = (bi & 1) * 2;
            bbase[i] = (bi * 32 + nn * 4) * 2 + reg;
        }
    }

    float acc[4][4][4];
#pragma unroll
    for (int i = 0; i < 4; i++)
#pragma unroll
        for (int j = 0; j < 4; j++)
#pragma unroll
            for (int r = 0; r < 4; r++) acc[i][j][r] = 0.f;

    float4 ra[2], rb[2];
#pragma unroll
    for (int i = 0; i < 2; i++) {
        ra[i] = *(const float4*)agp[i];
        rb[i] = *(const float4*)bgp[i];
    }
#pragma unroll
    for (int i = 0; i < 2; i++) {
        const float av[4] = {ra[i].x, ra[i].y, ra[i].z, ra[i].w};
        const float bv[4] = {rb[i].x, rb[i].y, rb[i].z, rb[i].w};
#pragma unroll
        for (int q = 0; q < 4; q++) {
            sA[0][abase[i] + ((q ^ arot[i]) << 2)] = f32_to_tf32(av[q]);
            sB[0][bbase[i] + ((q ^ brot[i]) << 1)] = f32_to_tf32(bv[q]);
        }
    }
    __syncthreads();

    const int nch = K / CH_K;
    for (int c = 0; c < nch; c++) {
        const int cur = c & 1;
        if (c + 1 < nch) {
            const int ko = (c + 1) * CH_K;
#pragma unroll
            for (int i = 0; i < 2; i++) {
                ra[i] = *(const float4*)(agp[i] + ko);
                rb[i] = *(const float4*)(bgp[i] + ko);
            }
        }

#pragma unroll
        for (int s = 0; s < 2; s++) {
            uint32_t af[4][4];
            uint32_t bf[4][2];
#pragma unroll
            for (int i = 0; i < 4; i++) {
                const int bi = (warpM * 4 + i) * 2 + s;
                const int l  = lane ^ ((bi & 1) * 2);
                *(uint4*)af[i] = *(const uint4*)&sA[cur][(bi * 32 + l) * 4];
            }
#pragma unroll
            for (int j = 0; j < 4; j++) {
                const int bi = (warpN * 4 + j) * 2 + s;
                const int l  = lane ^ ((bi & 1) * 2);
                *(uint2*)bf[j] = *(const uint2*)&sB[cur][(bi * 32 + l) * 2];
            }
#pragma unroll
            for (int i = 0; i < 4; i++)
#pragma unroll
                for (int j = 0; j < 4; j++)
                    mma_tf32(acc[i][j], af[i], bf[j]);
        }

        if (c + 1 < nch) {
            const int nxt = cur ^ 1;
#pragma unroll
            for (int i = 0; i < 2; i++) {
                const float av[4] = {ra[i].x, ra[i].y, ra[i].z, ra[i].w};
                const float bv[4] = {rb[i].x, rb[i].y, rb[i].z, rb[i].w};
#pragma unroll
                for (int q = 0; q < 4; q++) {
                    sA[nxt][abase[i] + ((q ^ arot[i]) << 2)] = f32_to_tf32(av[q]);
                    sB[nxt][bbase[i] + ((q ^ brot[i]) << 1)] = f32_to_tf32(bv[q]);
                }
            }
        }
        __syncthreads();
    }

#pragma unroll
    for (int i = 0; i < 4; i++) {
        const int row = m0 + warpM * 64 + i * 16 + (lane >> 2);
#pragma unroll
        for (int j = 0; j < 4; j++) {
            const int col = n0 + warpN * 32 + j * 8 + (lane & 3) * 2;
            float2 v0 = make_float2(acc[i][j][0], acc[i][j][1]);
            float2 v1 = make_float2(acc[i][j][2], acc[i][j][3]);
            if (HAS_BIAS) {
                const float b0 = bias[col], b1 = bias[col + 1];
                v0.x += b0; v0.y += b1;
                v1.x += b0; v1.y += b1;
            }
            *(float2*)(C + (size_t)row * N + col) = v0;
            *(float2*)(C + (size_t)(row + 8) * N + col) = v1;
        }
    }
}

// ---------------------------------------------------------------------------
// Tensor-core flash attention, split-bf16 m16n8k16, Br=64 Bc=64.
// R11 structure (48 KB/CTA, 3 CTAs/SM) with COALESCED staging loads:
// K and Q use row = idx>>4, col4 = idx&15 so each LDG.128 warp instruction
// touches 4 cache lines (2 rows x 256B) instead of 32 — 8x fewer L1tex
// wavefronts and half the L2 sector traffic on the K path. V already
// row-contiguous. Fragment layouts identical to R11 (validated).
// ---------------------------------------------------------------------------
__global__ __launch_bounds__(128, 3) void flash_mma(
    const float* __restrict__ qkv, float* __restrict__ ctx)
{
    extern __shared__ uint32_t fsm[];
    uint32_t* sQh = fsm;             // 2048 words
    uint32_t* sQl = fsm + 2048;
    uint32_t* sKh = fsm + 4096;
    uint32_t* sKl = fsm + 6144;
    uint32_t* sVh = fsm + 8192;
    uint32_t* sVl = fsm + 10240;     // total 12288 words = 48 KB

    const int tid  = threadIdx.x;
    const int lane = tid & 31;
    const int wid  = tid >> 5;
    const int b = blockIdx.z, h = blockIdx.y;
    const int q0 = blockIdx.x * 64;

    const float* Qg = qkv + (size_t)b * SEQ * QKVLD + h * HDIM;
    const float* Kg = Qg + DIMS;
    const float* Vg = Qg + 2 * DIMS;

    const int slotC = ((lane >> 2) << 2) | ((lane & 3) ^ ((lane >> 3) & 3));
    // A (Q): bi = wid*4 + s, s<4 -> bi>>3 = wid>>1, bi>>4 = 0
    const int aoff = slotC ^ (((wid >> 1) & 1) << 2);
    // B (K and V): bi = nt*4 + s -> bi>>3 = nt>>1, bi>>4 = nt>>2
    int boff[8];
#pragma unroll
    for (int nt = 0; nt < 8; nt++)
        boff[nt] = slotC ^ ((((nt >> 1) & 1) << 2) | (((nt >> 2) & 1) << 3));

    // ---- stage Q (scaled 0.125, hi/lo bf16); coalesced: 16 lanes per row ----
#pragma unroll
    for (int i = 0; i < 8; i++) {
        const int idx = tid + i * 128;
        const int row = idx >> 4, k0 = (idx & 15) * 4;
        float4 v = *(const float4*)(Qg + (size_t)(q0 + row) * QKVLD + k0);
        const float x0 = v.x * 0.125f, x1 = v.y * 0.125f;
        const float x2 = v.z * 0.125f, x3 = v.w * 0.125f;
        const int bi = (row >> 4) * 4 + (k0 >> 4);
        const int rot = (((bi >> 3) & 1) << 2) | (((bi >> 4) & 1) << 3);
        const int scr = ((row & 7) >> 1) & 3;
        const int p0 = (k0 >> 1) & 3;                 // in {0,2}
        const int reg = ((row >> 3) & 1) + 2 * ((k0 >> 3) & 1);
        const int s0 = (((row & 7) << 2) | (p0 ^ scr)) ^ rot;
        const int s1 = (((row & 7) << 2) | ((p0 + 1) ^ scr)) ^ rot;
        const int a0 = (bi * 32 + s0) * 4 + reg;
        const int a1 = (bi * 32 + s1) * 4 + reg;
        sQh[a0] = pack2_bf16(x0, x1);
        sQh[a1] = pack2_bf16(x2, x3);
        sQl[a0] = pack2_bf16(x0 - bf16_round(x0), x1 - bf16_round(x1));
        sQl[a1] = pack2_bf16(x2 - bf16_round(x2), x3 - bf16_round(x3));
    }

    float oacc[8][4];
    float m_run[2], l_run[2];
#pragma unroll
    for (int nt = 0; nt < 8; nt++)
#pragma unroll
        for (int r = 0; r < 4; r++) oacc[nt][r] = 0.f;
    m_run[0] = m_run[1] = -1e30f;
    l_run[0] = l_run[1] = 0.f;

    for (int kv0 = 0; kv0 < SEQ; kv0 += 64) {
        __syncthreads();   // prior iter done with sK/sV (covers Q stage, iter 0)

        // ---- stage K (n=kv, k=hd); coalesced: 16 lanes per row ----
#pragma unroll
        for (int i = 0; i < 8; i++) {
            const int idx = tid + i * 128;
            const int n = idx >> 4, k0 = (idx & 15) * 4;
            float4 v = *(const float4*)(Kg + (size_t)(kv0 + n) * QKVLD + k0);
            const int bi = (n >> 3) * 4 + (k0 >> 4);
            const int rot = (((bi >> 3) & 1) << 2) | (((bi >> 4) & 1) << 3);
            const int scr = ((n & 7) >> 1) & 3;
            const int p0 = (k0 >> 1) & 3;
            const int reg = (k0 >> 3) & 1;
            const int s0 = (((n & 7) << 2) | (p0 ^ scr)) ^ rot;
            const int s1 = (((n & 7) << 2) | ((p0 + 1) ^ scr)) ^ rot;
            const int a0 = (bi * 32 + s0) * 2 + reg;
            const int a1 = (bi * 32 + s1) * 2 + reg;
            sKh[a0] = pack2_bf16(v.x, v.y);
            sKh[a1] = pack2_bf16(v.z, v.w);
            sKl[a0] = pack2_bf16(v.x - bf16_round(v.x), v.y - bf16_round(v.y));
            sKl[a1] = pack2_bf16(v.z - bf16_round(v.z), v.w - bf16_round(v.w));
        }
        // ---- stage V: B-layout (n=hd, k=kv); kv-pairs packed (already coalesced) ----
#pragma unroll
        for (int i = 0; i < 4; i++) {
            const int idx = tid + i * 128;          // 0..511
            const int hd4 = idx & 15, kvp = idx >> 4;
            const int kvr = kvp * 2;                // even kv row
            float4 ve = *(const float4*)(Vg + (size_t)(kv0 + kvr) * QKVLD + hd4 * 4);
            float4 vo = *(const float4*)(Vg + (size_t)(kv0 + kvr + 1) * QKVLD + hd4 * 4);
            const float es[4] = {ve.x, ve.y, ve.z, ve.w};
            const float os[4] = {vo.x, vo.y, vo.z, vo.w};
            const int pp  = (kvr >> 1) & 3;
            const int reg = (kvr >> 3) & 1;
#pragma unroll
            for (int q = 0; q < 4; q++) {
                const int n = hd4 * 4 + q;
                const int bi = (n >> 3) * 4 + (kvr >> 4);
                const int rot = (((bi >> 3) & 1) << 2) | (((bi >> 4) & 1) << 3);
                const int scr = ((n & 7) >> 1) & 3;
                const int sl = (((n & 7) << 2) | (pp ^ scr)) ^ rot;
                const int a = (bi * 32 + sl) * 2 + reg;
                sVh[a] = pack2_bf16(es[q], os[q]);
                sVl[a] = pack2_bf16(es[q] - bf16_round(es[q]),
                                    os[q] - bf16_round(os[q]));
            }
        }
        __syncthreads();

        // ---- S = (Q*scale) @ K^T : 4 k16-steps x 8 kv-tiles, 3-term ----
        float sf[8][4];
#pragma unroll
        for (int nt = 0; nt < 8; nt++)
#pragma unroll
            for (int r = 0; r < 4; r++) sf[nt][r] = 0.f;

#pragma unroll
        for (int s = 0; s < 4; s++) {
            uint32_t aH[4], aL[4];
            *(uint4*)aH = *(const uint4*)&sQh[((wid * 4 + s) * 32 + aoff) * 4];
            *(uint4*)aL = *(const uint4*)&sQl[((wid * 4 + s) * 32 + aoff) * 4];
#pragma unroll
            for (int nt = 0; nt < 8; nt++) {
                uint32_t bH[2], bL[2];
                *(uint2*)bH = *(const uint2*)&sKh[((nt * 4 + s) * 32 + boff[nt]) * 2];
                *(uint2*)bL = *(const uint2*)&sKl[((nt * 4 + s) * 32 + boff[nt]) * 2];
                mma_bf16(sf[nt], aH, bH);
                mma_bf16(sf[nt], aH, bL);
                mma_bf16(sf[nt], aL, bH);
            }
        }

        // ---- online softmax (rows lane>>2, +8) ----
#pragma unroll
        for (int hf = 0; hf < 2; hf++) {
            float tm = -1e30f;
#pragma unroll
            for (int nt = 0; nt < 8; nt++)
                tm = fmaxf(tm, fmaxf(sf[nt][hf * 2], sf[nt][hf * 2 + 1]));
            tm = fmaxf(tm, __shfl_xor_sync(0xffffffffu, tm, 1));
            tm = fmaxf(tm, __shfl_xor_sync(0xffffffffu, tm, 2));
            const float mn  = fmaxf(m_run[hf], tm);
            const float fac = __expf(m_run[hf] - mn);
            float sum = 0.f;
#pragma unroll
            for (int nt = 0; nt < 8; nt++) {
#pragma unroll
                for (int j = 0; j < 2; j++) {
                    const float p = __expf(sf[nt][hf * 2 + j] - mn);
                    sf[nt][hf * 2 + j] = p;
                    sum += p;
                }
            }
            sum += __shfl_xor_sync(0xffffffffu, sum, 1);
            sum += __shfl_xor_sync(0xffffffffu, sum, 2);
            l_run[hf] = l_run[hf] * fac + sum;
            m_run[hf] = mn;
#pragma unroll
            for (int nt = 0; nt < 8; nt++) {
                oacc[nt][hf * 2]     *= fac;
                oacc[nt][hf * 2 + 1] *= fac;
            }
        }

        // ---- O += P @ V: P C-frag -> bf16 A-frag by packing (no shfl) ----
#pragma unroll
        for (int s = 0; s < 4; s++) {
            const float* p0 = sf[2 * s];
            const float* p1 = sf[2 * s + 1];
            uint32_t aH[4], aL[4];
            aH[0] = pack2_bf16(p0[0], p0[1]);
            aH[1] = pack2_bf16(p0[2], p0[3]);
            aH[2] = pack2_bf16(p1[0], p1[1]);
            aH[3] = pack2_bf16(p1[2], p1[3]);
            aL[0] = pack2_bf16(p0[0] - bf16_round(p0[0]), p0[1] - bf16_round(p0[1]));
            aL[1] = pack2_bf16(p0[2] - bf16_round(p0[2]), p0[3] - bf16_round(p0[3]));
            aL[2] = pack2_bf16(p1[0] - bf16_round(p1[0]), p1[1] - bf16_round(p1[1]));
            aL[3] = pack2_bf16(p1[2] - bf16_round(p1[2]), p1[3] - bf16_round(p1[3]));
#pragma unroll
            for (int nt = 0; nt < 8; nt++) {
                uint32_t vH[2], vL[2];
                *(uint2*)vH = *(const uint2*)&sVh[((nt * 4 + s) * 32 + boff[nt]) * 2];
                *(uint2*)vL = *(const uint2*)&sVl[((nt * 4 + s) * 32 + boff[nt]) * 2];
                mma_bf16(oacc[nt], aH, vH);
                mma_bf16(oacc[nt], aH, vL);
                mma_bf16(oacc[nt], aL, vH);
            }
        }
    }

    // ---- normalize + write ctx[b][q][h*64 + d] ----
    const float inv0 = 1.0f / l_run[0];
    const float inv1 = 1.0f / l_run[1];
    const int row0 = q0 + wid * 16 + (lane >> 2);
#pragma unroll
    for (int nt = 0; nt < 8; nt++) {
        const int col = h * HDIM + nt * 8 + 2 * (lane & 3);
        *(float2*)(ctx + ((size_t)b * SEQ + row0) * DIMS + col) =
            make_float2(oacc[nt][0] * inv0, oacc[nt][1] * inv0);
        *(float2*)(ctx + ((size_t)b * SEQ + row0 + 8) * DIMS + col) =
            make_float2(oacc[nt][2] * inv1, oacc[nt][3] * inv1);
    }
}

// ---------------------------------------------------------------------------
extern "C" void kernel_launch(void* const* d_in, const int* in_sizes, int n_in,
                              void* d_out, int out_size)
{
    const float* x      = (const float*)d_in[0];
    const float* w_qkv  = (const float*)d_in[1];
    const float* w_proj = (const float*)d_in[2];
    const float* b_proj = (const float*)d_in[3];
    float* out = (float*)d_out;

    float *qkv, *ctx, *wqkvT, *wprojT;
    cudaGetSymbolAddress((void**)&qkv, g_qkv);
    cudaGetSymbolAddress((void**)&ctx, g_ctx);
    cudaGetSymbolAddress((void**)&wqkvT, g_wqkvT);
    cudaGetSymbolAddress((void**)&wprojT, g_wprojT);

    const int M = BATCH * SEQ;

    transpose_k<<<dim3(QKVLD / 32, DIMS / 32), dim3(32, 8)>>>(w_qkv, wqkvT, DIMS, QKVLD);
    transpose_k<<<dim3(DIMS / 32, DIMS / 32), dim3(32, 8)>>>(w_proj, wprojT, DIMS, DIMS);

    gemm_mma<false><<<dim3(QKVLD / 128, M / 128), 256>>>(
        x, wqkvT, nullptr, qkv, M, QKVLD, DIMS);

    const int fsmem = 12288 * 4;   // 48 KB
    cudaFuncSetAttribute(flash_mma, cudaFuncAttributeMaxDynamicSharedMemorySize,
                         fsmem);
    flash_mma<<<dim3(SEQ / 64, NHEADS, BATCH), 128, fsmem>>>(qkv, ctx);

    gemm_mma<true><<<dim3(DIMS / 128, M / 128), 256>>>(
        ctx, wprojT, b_proj, out, M, DIMS, DIMS);
}

// round 17
// speedup vs baseline: 1.5318x; 1.0539x over previous
#include <cuda_runtime.h>
#include <cuda_bf16.h>
#include <cstdint>
#include <math.h>

#define DIMS    1024
#define SEQ     2048
#define BATCH   2
#define NHEADS  16
#define HDIM    64
#define QKVLD   3072

// ---------------------------------------------------------------------------
// Scratch (allocation-free rule: __device__ globals)
// ---------------------------------------------------------------------------
__device__ float g_qkv[(size_t)BATCH * SEQ * QKVLD];
__device__ float g_ctx[(size_t)BATCH * SEQ * DIMS];
__device__ float g_wqkvT[(size_t)QKVLD * DIMS];
__device__ float g_wprojT[(size_t)DIMS * DIMS];

__device__ __forceinline__ uint32_t f32_to_tf32(float f) {
    uint32_t u;
    asm("cvt.rna.tf32.f32 %0, %1;" : "=r"(u) : "f"(f));
    return u;
}

__device__ __forceinline__ void mma_tf32(float* d, const uint32_t* a, const uint32_t* b) {
    asm volatile(
        "mma.sync.aligned.m16n8k8.row.col.f32.tf32.tf32.f32 "
        "{%0,%1,%2,%3}, {%4,%5,%6,%7}, {%8,%9}, {%0,%1,%2,%3};"
        : "+f"(d[0]), "+f"(d[1]), "+f"(d[2]), "+f"(d[3])
        : "r"(a[0]), "r"(a[1]), "r"(a[2]), "r"(a[3]), "r"(b[0]), "r"(b[1]));
}

// bf16 m16n8k16 mma (sm_80+)
__device__ __forceinline__ void mma_bf16(float* d, const uint32_t* a, const uint32_t* b) {
    asm volatile(
        "mma.sync.aligned.m16n8k16.row.col.f32.bf16.bf16.f32 "
        "{%0,%1,%2,%3}, {%4,%5,%6,%7}, {%8,%9}, {%0,%1,%2,%3};"
        : "+f"(d[0]), "+f"(d[1]), "+f"(d[2]), "+f"(d[3])
        : "r"(a[0]), "r"(a[1]), "r"(a[2]), "r"(a[3]), "r"(b[0]), "r"(b[1]));
}

// pack two floats to bf16x2 word: low half = e (even k), high half = o (odd k).
__device__ __forceinline__ uint32_t pack2_bf16(float e, float o) {
    __nv_bfloat162 p = __float22bfloat162_rn(make_float2(e, o));
    return *reinterpret_cast<uint32_t*>(&p);
}
__device__ __forceinline__ float bf16_round(float x) {
    return __bfloat162float(__float2bfloat16_rn(x));
}

// ---------------------------------------------------------------------------
// Weight transpose (unchanged).
// ---------------------------------------------------------------------------
__global__ __launch_bounds__(256) void transpose_k(
    const float* __restrict__ in, float* __restrict__ out, int R, int C)
{
    __shared__ float t[32][33];
    int x = blockIdx.x * 32 + threadIdx.x;
    int y = blockIdx.y * 32 + threadIdx.y;
#pragma unroll
    for (int j = 0; j < 32; j += 8)
        t[threadIdx.y + j][threadIdx.x] = in[(size_t)(y + j) * C + x];
    __syncthreads();
    int x2 = blockIdx.y * 32 + threadIdx.x;
    int y2 = blockIdx.x * 32 + threadIdx.y;
#pragma unroll
    for (int j = 0; j < 32; j += 8)
        out[(size_t)(y2 + j) * R + x2] = t[threadIdx.x][threadIdx.y + j];
}

// ---------------------------------------------------------------------------
// tf32 mma.sync GEMM (unchanged — validated).
// ---------------------------------------------------------------------------
#define CH_K 16

template <bool HAS_BIAS>
__global__ __launch_bounds__(256) void gemm_mma(
    const float* __restrict__ A, const float* __restrict__ BT,
    const float* __restrict__ bias, float* __restrict__ C,
    int M, int N, int K)
{
    __shared__ uint32_t sA[2][128 * CH_K];
    __shared__ uint32_t sB[2][128 * CH_K];

    const int tid   = threadIdx.x;
    const int lane  = tid & 31;
    const int wid   = tid >> 5;
    const int warpM = wid >> 2;
    const int warpN = wid & 3;
    const int m0 = blockIdx.y * 128;
    const int n0 = blockIdx.x * 128;

    const float* agp[2];
    const float* bgp[2];
    int abase[2], bbase[2], arot[2], brot[2];
#pragma unroll
    for (int i = 0; i < 2; i++) {
        const int idx = tid + i * 256;
        const int row = idx >> 2;
        const int k0  = (idx & 3) << 2;
        agp[i] = A + (size_t)(m0 + row) * K + k0;
        {
            const int mt = row >> 4, rr = row & 15, s = k0 >> 3;
            const int bi = mt * 2 + s;
            const int reg = (rr >> 3) + 2 * ((k0 >> 2) & 1);
            arot[i]  = (bi & 1) * 2;
            abase[i] = (bi * 32 + (rr & 7) * 4) * 4 + reg;
        }
        bgp[i] = BT + (size_t)(n0 + row) * K + k0;
        {
            const int nt = row >> 3, nn = row & 7, s = k0 >> 3;
            const int bi = nt * 2 + s;
            const int reg = (k0 >> 2) & 1;
            brot[i]  = (bi & 1) * 2;
            bbase[i] = (bi * 32 + nn * 4) * 2 + reg;
        }
    }

    float acc[4][4][4];
#pragma unroll
    for (int i = 0; i < 4; i++)
#pragma unroll
        for (int j = 0; j < 4; j++)
#pragma unroll
            for (int r = 0; r < 4; r++) acc[i][j][r] = 0.f;

    float4 ra[2], rb[2];
#pragma unroll
    for (int i = 0; i < 2; i++) {
        ra[i] = *(const float4*)agp[i];
        rb[i] = *(const float4*)bgp[i];
    }
#pragma unroll
    for (int i = 0; i < 2; i++) {
        const float av[4] = {ra[i].x, ra[i].y, ra[i].z, ra[i].w};
        const float bv[4] = {rb[i].x, rb[i].y, rb[i].z, rb[i].w};
#pragma unroll
        for (int q = 0; q < 4; q++) {
            sA[0][abase[i] + ((q ^ arot[i]) << 2)] = f32_to_tf32(av[q]);
            sB[0][bbase[i] + ((q ^ brot[i]) << 1)] = f32_to_tf32(bv[q]);
        }
    }
    __syncthreads();

    const int nch = K / CH_K;
    for (int c = 0; c < nch; c++) {
        const int cur = c & 1;
        if (c + 1 < nch) {
            const int ko = (c + 1) * CH_K;
#pragma unroll
            for (int i = 0; i < 2; i++) {
                ra[i] = *(const float4*)(agp[i] + ko);
                rb[i] = *(const float4*)(bgp[i] + ko);
            }
        }

#pragma unroll
        for (int s = 0; s < 2; s++) {
            uint32_t af[4][4];
            uint32_t bf[4][2];
#pragma unroll
            for (int i = 0; i < 4; i++) {
                const int bi = (warpM * 4 + i) * 2 + s;
                const int l  = lane ^ ((bi & 1) * 2);
                *(uint4*)af[i] = *(const uint4*)&sA[cur][(bi * 32 + l) * 4];
            }
#pragma unroll
            for (int j = 0; j < 4; j++) {
                const int bi = (warpN * 4 + j) * 2 + s;
                const int l  = lane ^ ((bi & 1) * 2);
                *(uint2*)bf[j] = *(const uint2*)&sB[cur][(bi * 32 + l) * 2];
            }
#pragma unroll
            for (int i = 0; i < 4; i++)
#pragma unroll
                for (int j = 0; j < 4; j++)
                    mma_tf32(acc[i][j], af[i], bf[j]);
        }

        if (c + 1 < nch) {
            const int nxt = cur ^ 1;
#pragma unroll
            for (int i = 0; i < 2; i++) {
                const float av[4] = {ra[i].x, ra[i].y, ra[i].z, ra[i].w};
                const float bv[4] = {rb[i].x, rb[i].y, rb[i].z, rb[i].w};
#pragma unroll
                for (int q = 0; q < 4; q++) {
                    sA[nxt][abase[i] + ((q ^ arot[i]) << 2)] = f32_to_tf32(av[q]);
                    sB[nxt][bbase[i] + ((q ^ brot[i]) << 1)] = f32_to_tf32(bv[q]);
                }
            }
        }
        __syncthreads();
    }

#pragma unroll
    for (int i = 0; i < 4; i++) {
        const int row = m0 + warpM * 64 + i * 16 + (lane >> 2);
#pragma unroll
        for (int j = 0; j < 4; j++) {
            const int col = n0 + warpN * 32 + j * 8 + (lane & 3) * 2;
            float2 v0 = make_float2(acc[i][j][0], acc[i][j][1]);
            float2 v1 = make_float2(acc[i][j][2], acc[i][j][3]);
            if (HAS_BIAS) {
                const float b0 = bias[col], b1 = bias[col + 1];
                v0.x += b0; v0.y += b1;
                v1.x += b0; v1.y += b1;
            }
            *(float2*)(C + (size_t)row * N + col) = v0;
            *(float2*)(C + (size_t)(row + 8) * N + col) = v1;
        }
    }
}

// ---------------------------------------------------------------------------
// Tensor-core flash attention, split-bf16 m16n8k16, Br=128 Bc=64.
// Warp owns 32 q-rows (2 m-tiles) — K/V fragment loads amortized over 2x mma
// (crossbar bytes per unit work cut 1.8x vs Br=64). 64 KB smem/CTA, 2 CTA/SM,
// __launch_bounds__(128,2) -> 255-reg budget. Coalesced staging (R15).
// Fragment layouts identical to R11/R15 family (validated); Q bi in [0,32).
// ---------------------------------------------------------------------------
__global__ __launch_bounds__(128, 2) void flash_mma(
    const float* __restrict__ qkv, float* __restrict__ ctx)
{
    extern __shared__ uint32_t fsm[];
    uint32_t* sQh = fsm;             // 4096 words (128x64 bf16)
    uint32_t* sQl = fsm + 4096;
    uint32_t* sKh = fsm + 8192;      // 2048 words (64x64 bf16)
    uint32_t* sKl = fsm + 10240;
    uint32_t* sVh = fsm + 12288;
    uint32_t* sVl = fsm + 14336;     // total 16384 words = 64 KB

    const int tid  = threadIdx.x;
    const int lane = tid & 31;
    const int wid  = tid >> 5;
    const int b = blockIdx.z, h = blockIdx.y;
    const int q0 = blockIdx.x * 128;

    const float* Qg = qkv + (size_t)b * SEQ * QKVLD + h * HDIM;
    const float* Kg = Qg + DIMS;
    const float* Vg = Qg + 2 * DIMS;

    const int slotC = ((lane >> 2) << 2) | ((lane & 3) ^ ((lane >> 3) & 3));
    // A (Q): bi = (2*wid+mi)*4 + s, s<4, mi<2 -> bi>>3 = wid, bi>>4 = wid>>1
    // (identical for mi=0,1 since 8w+4mi+s stays within [8w, 8w+8))
    const int aoff = slotC ^ (((wid & 1) << 2) | (((wid >> 1) & 1) << 3));
    // B (K and V): bi = nt*4 + s -> bi>>3 = nt>>1, bi>>4 = nt>>2
    int boff[8];
#pragma unroll
    for (int nt = 0; nt < 8; nt++)
        boff[nt] = slotC ^ ((((nt >> 1) & 1) << 2) | (((nt >> 2) & 1) << 3));

    // ---- stage Q (scaled 0.125, hi/lo bf16); 128 rows, coalesced ----
#pragma unroll
    for (int i = 0; i < 16; i++) {
        const int idx = tid + i * 128;          // 0..2047
        const int row = idx >> 4, k0 = (idx & 15) * 4;
        float4 v = *(const float4*)(Qg + (size_t)(q0 + row) * QKVLD + k0);
        const float x0 = v.x * 0.125f, x1 = v.y * 0.125f;
        const float x2 = v.z * 0.125f, x3 = v.w * 0.125f;
        const int bi = (row >> 4) * 4 + (k0 >> 4);      // 0..31
        const int rot = (((bi >> 3) & 1) << 2) | (((bi >> 4) & 1) << 3);
        const int scr = ((row & 7) >> 1) & 3;
        const int p0 = (k0 >> 1) & 3;                   // in {0,2}
        const int reg = ((row >> 3) & 1) + 2 * ((k0 >> 3) & 1);
        const int s0 = (((row & 7) << 2) | (p0 ^ scr)) ^ rot;
        const int s1 = (((row & 7) << 2) | ((p0 + 1) ^ scr)) ^ rot;
        const int a0 = (bi * 32 + s0) * 4 + reg;
        const int a1 = (bi * 32 + s1) * 4 + reg;
        sQh[a0] = pack2_bf16(x0, x1);
        sQh[a1] = pack2_bf16(x2, x3);
        sQl[a0] = pack2_bf16(x0 - bf16_round(x0), x1 - bf16_round(x1));
        sQl[a1] = pack2_bf16(x2 - bf16_round(x2), x3 - bf16_round(x3));
    }

    float oacc[2][8][4];
    float m_run[2][2], l_run[2][2];
#pragma unroll
    for (int mi = 0; mi < 2; mi++) {
#pragma unroll
        for (int nt = 0; nt < 8; nt++)
#pragma unroll
            for (int r = 0; r < 4; r++) oacc[mi][nt][r] = 0.f;
        m_run[mi][0] = m_run[mi][1] = -1e30f;
        l_run[mi][0] = l_run[mi][1] = 0.f;
    }

    for (int kv0 = 0; kv0 < SEQ; kv0 += 64) {
        __syncthreads();   // prior iter done with sK/sV (covers Q stage, iter 0)

        // ---- stage K (n=kv, k=hd); coalesced: 16 lanes per row ----
#pragma unroll
        for (int i = 0; i < 8; i++) {
            const int idx = tid + i * 128;
            const int n = idx >> 4, k0 = (idx & 15) * 4;
            float4 v = *(const float4*)(Kg + (size_t)(kv0 + n) * QKVLD + k0);
            const int bi = (n >> 3) * 4 + (k0 >> 4);
            const int rot = (((bi >> 3) & 1) << 2) | (((bi >> 4) & 1) << 3);
            const int scr = ((n & 7) >> 1) & 3;
            const int p0 = (k0 >> 1) & 3;
            const int reg = (k0 >> 3) & 1;
            const int s0 = (((n & 7) << 2) | (p0 ^ scr)) ^ rot;
            const int s1 = (((n & 7) << 2) | ((p0 + 1) ^ scr)) ^ rot;
            const int a0 = (bi * 32 + s0) * 2 + reg;
            const int a1 = (bi * 32 + s1) * 2 + reg;
            sKh[a0] = pack2_bf16(v.x, v.y);
            sKh[a1] = pack2_bf16(v.z, v.w);
            sKl[a0] = pack2_bf16(v.x - bf16_round(v.x), v.y - bf16_round(v.y));
            sKl[a1] = pack2_bf16(v.z - bf16_round(v.z), v.w - bf16_round(v.w));
        }
        // ---- stage V: B-layout (n=hd, k=kv); kv-pairs packed ----
#pragma unroll
        for (int i = 0; i < 4; i++) {
            const int idx = tid + i * 128;
            const int hd4 = idx & 15, kvp = idx >> 4;
            const int kvr = kvp * 2;
            float4 ve = *(const float4*)(Vg + (size_t)(kv0 + kvr) * QKVLD + hd4 * 4);
            float4 vo = *(const float4*)(Vg + (size_t)(kv0 + kvr + 1) * QKVLD + hd4 * 4);
            const float es[4] = {ve.x, ve.y, ve.z, ve.w};
            const float os[4] = {vo.x, vo.y, vo.z, vo.w};
            const int pp  = (kvr >> 1) & 3;
            const int reg = (kvr >> 3) & 1;
#pragma unroll
            for (int q = 0; q < 4; q++) {
                const int n = hd4 * 4 + q;
                const int bi = (n >> 3) * 4 + (kvr >> 4);
                const int rot = (((bi >> 3) & 1) << 2) | (((bi >> 4) & 1) << 3);
                const int scr = ((n & 7) >> 1) & 3;
                const int sl = (((n & 7) << 2) | (pp ^ scr)) ^ rot;
                const int a = (bi * 32 + sl) * 2 + reg;
                sVh[a] = pack2_bf16(es[q], os[q]);
                sVl[a] = pack2_bf16(es[q] - bf16_round(es[q]),
                                    os[q] - bf16_round(os[q]));
            }
        }
        __syncthreads();

        // ---- S = (Q*scale) @ K^T : 2 m-tiles share each K-fragment load ----
        float sf[2][8][4];
#pragma unroll
        for (int mi = 0; mi < 2; mi++)
#pragma unroll
            for (int nt = 0; nt < 8; nt++)
#pragma unroll
                for (int r = 0; r < 4; r++) sf[mi][nt][r] = 0.f;

#pragma unroll
        for (int s = 0; s < 4; s++) {
            uint32_t aH[2][4], aL[2][4];
#pragma unroll
            for (int mi = 0; mi < 2; mi++) {
                const int bi = (2 * wid + mi) * 4 + s;
                *(uint4*)aH[mi] = *(const uint4*)&sQh[(bi * 32 + aoff) * 4];
                *(uint4*)aL[mi] = *(const uint4*)&sQl[(bi * 32 + aoff) * 4];
            }
#pragma unroll
            for (int nt = 0; nt < 8; nt++) {
                uint32_t bH[2], bL[2];
                *(uint2*)bH = *(const uint2*)&sKh[((nt * 4 + s) * 32 + boff[nt]) * 2];
                *(uint2*)bL = *(const uint2*)&sKl[((nt * 4 + s) * 32 + boff[nt]) * 2];
#pragma unroll
                for (int mi = 0; mi < 2; mi++) {
                    mma_bf16(sf[mi][nt], aH[mi], bH);
                    mma_bf16(sf[mi][nt], aH[mi], bL);
                    mma_bf16(sf[mi][nt], aL[mi], bH);
                }
            }
        }

        // ---- online softmax per m-tile (rows lane>>2, +8) ----
#pragma unroll
        for (int mi = 0; mi < 2; mi++) {
#pragma unroll
            for (int hf = 0; hf < 2; hf++) {
                float tm = -1e30f;
#pragma unroll
                for (int nt = 0; nt < 8; nt++)
                    tm = fmaxf(tm, fmaxf(sf[mi][nt][hf * 2], sf[mi][nt][hf * 2 + 1]));
                tm = fmaxf(tm, __shfl_xor_sync(0xffffffffu, tm, 1));
                tm = fmaxf(tm, __shfl_xor_sync(0xffffffffu, tm, 2));
                const float mn  = fmaxf(m_run[mi][hf], tm);
                const float fac = __expf(m_run[mi][hf] - mn);
                float sum = 0.f;
#pragma unroll
                for (int nt = 0; nt < 8; nt++) {
#pragma unroll
                    for (int j = 0; j < 2; j++) {
                        const float p = __expf(sf[mi][nt][hf * 2 + j] - mn);
                        sf[mi][nt][hf * 2 + j] = p;
                        sum += p;
                    }
                }
                sum += __shfl_xor_sync(0xffffffffu, sum, 1);
                sum += __shfl_xor_sync(0xffffffffu, sum, 2);
                l_run[mi][hf] = l_run[mi][hf] * fac + sum;
                m_run[mi][hf] = mn;
#pragma unroll
                for (int nt = 0; nt < 8; nt++) {
                    oacc[mi][nt][hf * 2]     *= fac;
                    oacc[mi][nt][hf * 2 + 1] *= fac;
                }
            }
        }

        // ---- O += P @ V: V-frags shared across both m-tiles ----
#pragma unroll
        for (int s = 0; s < 4; s++) {
            uint32_t aH[2][4], aL[2][4];
#pragma unroll
            for (int mi = 0; mi < 2; mi++) {
                const float* p0 = sf[mi][2 * s];
                const float* p1 = sf[mi][2 * s + 1];
                aH[mi][0] = pack2_bf16(p0[0], p0[1]);
                aH[mi][1] = pack2_bf16(p0[2], p0[3]);
                aH[mi][2] = pack2_bf16(p1[0], p1[1]);
                aH[mi][3] = pack2_bf16(p1[2], p1[3]);
                aL[mi][0] = pack2_bf16(p0[0] - bf16_round(p0[0]), p0[1] - bf16_round(p0[1]));
                aL[mi][1] = pack2_bf16(p0[2] - bf16_round(p0[2]), p0[3] - bf16_round(p0[3]));
                aL[mi][2] = pack2_bf16(p1[0] - bf16_round(p1[0]), p1[1] - bf16_round(p1[1]));
                aL[mi][3] = pack2_bf16(p1[2] - bf16_round(p1[2]), p1[3] - bf16_round(p1[3]));
            }
#pragma unroll
            for (int nt = 0; nt < 8; nt++) {
                uint32_t vH[2], vL[2];
                *(uint2*)vH = *(const uint2*)&sVh[((nt * 4 + s) * 32 + boff[nt]) * 2];
                *(uint2*)vL = *(const uint2*)&sVl[((nt * 4 + s) * 32 + boff[nt]) * 2];
#pragma unroll
                for (int mi = 0; mi < 2; mi++) {
                    mma_bf16(oacc[mi][nt], aH[mi], vH);
                    mma_bf16(oacc[mi][nt], aH[mi], vL);
                    mma_bf16(oacc[mi][nt], aL[mi], vH);
                }
            }
        }
    }

    // ---- normalize + write ctx[b][q][h*64 + d] ----
#pragma unroll
    for (int mi = 0; mi < 2; mi++) {
        const float inv0 = 1.0f / l_run[mi][0];
        const float inv1 = 1.0f / l_run[mi][1];
        const int row0 = q0 + wid * 32 + mi * 16 + (lane >> 2);
#pragma unroll
        for (int nt = 0; nt < 8; nt++) {
            const int col = h * HDIM + nt * 8 + 2 * (lane & 3);
            *(float2*)(ctx + ((size_t)b * SEQ + row0) * DIMS + col) =
                make_float2(oacc[mi][nt][0] * inv0, oacc[mi][nt][1] * inv0);
            *(float2*)(ctx + ((size_t)b * SEQ + row0 + 8) * DIMS + col) =
                make_float2(oacc[mi][nt][2] * inv1, oacc[mi][nt][3] * inv1);
        }
    }
}

// ---------------------------------------------------------------------------
extern "C" void kernel_launch(void* const* d_in, const int* in_sizes, int n_in,
                              void* d_out, int out_size)
{
    const float* x      = (const float*)d_in[0];
    const float* w_qkv  = (const float*)d_in[1];
    const float* w_proj = (const float*)d_in[2];
    const float* b_proj = (const float*)d_in[3];
    float* out = (float*)d_out;

    float *qkv, *ctx, *wqkvT, *wprojT;
    cudaGetSymbolAddress((void**)&qkv, g_qkv);
    cudaGetSymbolAddress((void**)&ctx, g_ctx);
    cudaGetSymbolAddress((void**)&wqkvT, g_wqkvT);
    cudaGetSymbolAddress((void**)&wprojT, g_wprojT);

    const int M = BATCH * SEQ;

    transpose_k<<<dim3(QKVLD / 32, DIMS / 32), dim3(32, 8)>>>(w_qkv, wqkvT, DIMS, QKVLD);
    transpose_k<<<dim3(DIMS / 32, DIMS / 32), dim3(32, 8)>>>(w_proj, wprojT, DIMS, DIMS);

    gemm_mma<false><<<dim3(QKVLD / 128, M / 128), 256>>>(
        x, wqkvT, nullptr, qkv, M, QKVLD, DIMS);

    const int fsmem = 16384 * 4;   // 64 KB
    cudaFuncSetAttribute(flash_mma, cudaFuncAttributeMaxDynamicSharedMemorySize,
                         fsmem);
    flash_mma<<<dim3(SEQ / 128, NHEADS, BATCH), 128, fsmem>>>(qkv, ctx);

    gemm_mma<true><<<dim3(DIMS / 128, M / 128), 256>>>(
        ctx, wprojT, b_proj, out, M, DIMS, DIMS);
}